// round 1
// baseline (speedup 1.0000x reference)
#include <cuda_runtime.h>
#include <cstdint>
#include <cstddef>

// Problem constants
#define BATCH   4
#define CIN     64
#define COUT    128
#define HH      64
#define WW      1024
#define HO      32
#define WO      512
#define NPIX    65536          // BATCH*HO*WO
#define KTOT    1024           // CIN*16
#define OUT0    8388608        // BATCH*COUT*HO*WO
#define AZI_C   0.006135923151542565f   // 2*pi/1024
#define INC_C   0.0073f

// scratch: mT[k][n], k = c*16 + u*4 + v, n = pixel index (b*16384 + ho*512 + wo)
__device__ float g_m[(size_t)KTOT * NPIX];

// ---- packed f32x2 helpers ----
__device__ __forceinline__ unsigned long long pk2(float a, float b) {
    unsigned long long d;
    asm("mov.b64 %0, {%1, %2};" : "=l"(d) : "r"(__float_as_uint(a)), "r"(__float_as_uint(b)));
    return d;
}
__device__ __forceinline__ void fma2(unsigned long long& d, unsigned long long a, unsigned long long b) {
    asm("fma.rn.f32x2 %0, %1, %2, %0;" : "+l"(d) : "l"(a), "l"(b));
}

// =====================================================================
// Kernel 1: compute modulation weights w, write m = w * x_patch to g_m,
//           and write r_center.
// grid (16, 32, 4), 256 threads. Dynamic smem.
// smem layout (floats):
//   ws   [512][68]   (w per combo=pos*32+px, padded stride)
//   W2s  [64][64]
//   As   [16][64]
//   W10s [64], b1s[64], b2s[64]
//   rs   [4][66]
// =====================================================================
#define WS_STRIDE 68
#define SM1_FLOATS (512*WS_STRIDE + 4096 + 1024 + 64 + 64 + 64 + 4*66)

__global__ void __launch_bounds__(256, 1)
k1_weights(const float* __restrict__ x, const float* __restrict__ r,
           const float* __restrict__ W1, const float* __restrict__ b1,
           const float* __restrict__ W2, const float* __restrict__ b2,
           float* __restrict__ rcout)
{
    extern __shared__ float sm[];
    float* ws   = sm;
    float* W2s  = ws   + 512*WS_STRIDE;
    float* As   = W2s  + 4096;
    float* W10s = As   + 1024;
    float* b1s  = W10s + 64;
    float* b2s  = b1s  + 64;
    float* rs   = b2s  + 64;     // [4][66]

    const int tid = threadIdx.x;
    const int ho  = blockIdx.y;
    const int bz  = blockIdx.z;
    const int wo0 = blockIdx.x * 32;

    // ---- loads ----
    for (int i = tid; i < 4096; i += 256) W2s[i] = W2[i];
    if (tid < 64) { W10s[tid] = W1[tid]; b1s[tid] = b1[tid]; b2s[tid] = b2[tid]; }
    for (int i = tid; i < 1024; i += 256) {
        int pos = i >> 6, j = i & 63;
        int u = pos >> 2, v = pos & 3;
        float du = (float)(u - 2), dv = (float)(v - 2);
        float ca = cosf(AZI_C * dv), sa = sinf(AZI_C * dv);
        float ci = cosf(INC_C * du), si = sinf(INC_C * du);
        As[i] = ca * ci * W1[j] + ca * si * W1[64 + j] + sa * W1[128 + j];
    }
    for (int i = tid; i < 4*66; i += 256) {
        int v = i / 66, cc = i % 66;
        int rowp = 2 * ho + v;                         // 0..65
        int row  = (rowp == 0) ? (HH - 1) : ((rowp == HH + 1) ? 0 : rowp - 1);
        int colp = 2 * wo0 + cc;                       // 0..1025
        float val;
        if (colp == 0 || colp == WW + 1) val = 100.0f;
        else val = r[((size_t)bz * HH + row) * WW + (colp - 1)];
        rs[i] = val;
    }
    __syncthreads();

    // ---- phase A: h (regs) -> w (smem) ----
    for (int cb = 0; cb < 2; cb++) {
        const int combo = tid + cb * 256;      // 0..511
        const int px  = combo & 31;
        const int pos = combo >> 5;            // 0..15
        const int u = pos >> 2, v = pos & 3;
        const float R  = rs[v * 66 + 2 * px + u];
        const float rc = rs[2 * 66 + 2 * px + 2];
        const float nrc = -rc;

        float h[64];
        const float* Ap = As + pos * 64;
        #pragma unroll
        for (int j = 0; j < 64; j++) {
            float t = fmaf(R, Ap[j], fmaf(nrc, W10s[j], b1s[j]));
            h[j] = (t > 0.0f) ? t : 0.2f * t;
        }

        float* wrow = ws + combo * WS_STRIDE;
        for (int c0 = 0; c0 < 64; c0 += 16) {
            unsigned long long acc[8];
            #pragma unroll
            for (int p = 0; p < 8; p++)
                acc[p] = pk2(b2s[c0 + 2*p], b2s[c0 + 2*p + 1]);
            #pragma unroll
            for (int j = 0; j < 64; j++) {
                unsigned long long hh = pk2(h[j], h[j]);
                const ulonglong2* wp = (const ulonglong2*)(W2s + j * 64 + c0);
                ulonglong2 qa = wp[0], qb = wp[1], qc = wp[2], qd = wp[3];
                fma2(acc[0], hh, qa.x); fma2(acc[1], hh, qa.y);
                fma2(acc[2], hh, qb.x); fma2(acc[3], hh, qb.y);
                fma2(acc[4], hh, qc.x); fma2(acc[5], hh, qc.y);
                fma2(acc[6], hh, qd.x); fma2(acc[7], hh, qd.y);
            }
            #pragma unroll
            for (int p = 0; p < 4; p++) {
                ulonglong2 o2; o2.x = acc[2*p]; o2.y = acc[2*p + 1];
                *(ulonglong2*)(wrow + c0 + 4*p) = o2;
            }
        }
    }
    __syncthreads();

    // ---- phase B: m = w * x_patch -> g_m (float4 along pixel dim) ----
    {
        const int c    = tid & 63;
        const int rest = tid >> 6;   // 0..3
        const size_t nbase = (size_t)bz * 16384 + (size_t)ho * 512 + wo0;

        int xr[4];
        #pragma unroll
        for (int v = 0; v < 4; v++) {
            int rowp = 2 * ho + v;
            xr[v] = (rowp == 0) ? (HH - 1) : ((rowp == HH + 1) ? 0 : rowp - 1);
        }
        const float* xc = x + ((size_t)(bz * CIN + c)) * (HH * WW);

        for (int it = 0; it < 32; it++) {
            int flat2 = rest + 4 * it;       // 0..127
            int pos = flat2 & 15, px4 = flat2 >> 4;   // px4 0..7
            int u = pos >> 2, v = pos & 3;
            int px0 = px4 * 4;

            const float* wsrc = ws + (size_t)(pos * 32 + px0) * WS_STRIDE + c;
            float w0 = wsrc[0];
            float w1 = wsrc[WS_STRIDE];
            float w2 = wsrc[2 * WS_STRIDE];
            float w3 = wsrc[3 * WS_STRIDE];

            const float* xrow = xc + (size_t)xr[v] * WW;
            float xv[4];
            #pragma unroll
            for (int i = 0; i < 4; i++) {
                int colp = 2 * (wo0 + px0 + i) + u;   // 0..1025
                xv[i] = (colp == 0 || colp == WW + 1) ? 0.0f : xrow[colp - 1];
            }
            float4 mm = make_float4(w0 * xv[0], w1 * xv[1], w2 * xv[2], w3 * xv[3]);
            *(float4*)(g_m + ((size_t)(c * 16 + pos)) * NPIX + nbase + px0) = mm;
        }

        if (rcout != nullptr && tid < 32) {
            rcout[nbase + tid] = rs[2 * 66 + 2 * tid + 2];
        }
    }
}

// =====================================================================
// Kernel 2: out[o][n] = bc[o] + sum_k Wc[o][k] * mT[k][n]
// Tile O=128 x N=128, Kc=16, f32x2 FFMA, register-prefetch pipeline.
// grid 512 blocks, 256 threads.
// =====================================================================
#define WSROW 132
__global__ void __launch_bounds__(256, 2)
k2_gemm(const float* __restrict__ Wc, const float* __restrict__ bc,
        float* __restrict__ out)
{
    __shared__ float Ws[16 * WSROW];   // [kk][o], padded
    __shared__ float ms[16 * 128];     // [kk][n]

    const int tid = threadIdx.x;
    const int tx = tid & 15;           // n group
    const int ty = tid >> 4;           // o group
    const int n0 = blockIdx.x * 128;

    unsigned long long acc[8][4];
    #pragma unroll
    for (int i = 0; i < 8; i++) {
        float bv = bc[ty * 8 + i];
        unsigned long long bp = pk2(bv, bv);
        #pragma unroll
        for (int j = 0; j < 4; j++) acc[i][j] = bp;
    }

    float4 rw[2], rm[2];

    // prefetch chunk 0
    #pragma unroll
    for (int p = 0; p < 2; p++) {
        int flat = tid * 4 + p * 1024;
        int o = flat >> 4, kk = flat & 15;
        rw[p] = *(const float4*)(Wc + (size_t)o * 1024 + kk);
        int mk = flat >> 7, col = flat & 127;
        rm[p] = *(const float4*)(g_m + (size_t)mk * NPIX + n0 + col);
    }
    #pragma unroll
    for (int p = 0; p < 2; p++) {
        int flat = tid * 4 + p * 1024;
        int o = flat >> 4, kk = flat & 15;
        Ws[(kk + 0) * WSROW + o] = rw[p].x;
        Ws[(kk + 1) * WSROW + o] = rw[p].y;
        Ws[(kk + 2) * WSROW + o] = rw[p].z;
        Ws[(kk + 3) * WSROW + o] = rw[p].w;
        int mk = flat >> 7, col = flat & 127;
        *(float4*)(ms + mk * 128 + col) = rm[p];
    }
    __syncthreads();

    for (int kc = 0; kc < 64; kc++) {
        if (kc < 63) {
            int k0 = (kc + 1) * 16;
            #pragma unroll
            for (int p = 0; p < 2; p++) {
                int flat = tid * 4 + p * 1024;
                int o = flat >> 4, kk = flat & 15;
                rw[p] = *(const float4*)(Wc + (size_t)o * 1024 + k0 + kk);
                int mk = flat >> 7, col = flat & 127;
                rm[p] = *(const float4*)(g_m + (size_t)(k0 + mk) * NPIX + n0 + col);
            }
        }
        #pragma unroll
        for (int kk = 0; kk < 16; kk++) {
            float4 a0 = *(const float4*)(Ws + kk * WSROW + ty * 8);
            float4 a1 = *(const float4*)(Ws + kk * WSROW + ty * 8 + 4);
            unsigned long long bq[4];
            #pragma unroll
            for (int j = 0; j < 4; j++)
                bq[j] = *(const unsigned long long*)(ms + kk * 128 + tx * 2 + j * 32);
            float av[8] = {a0.x, a0.y, a0.z, a0.w, a1.x, a1.y, a1.z, a1.w};
            #pragma unroll
            for (int i = 0; i < 8; i++) {
                unsigned long long hh = pk2(av[i], av[i]);
                fma2(acc[i][0], hh, bq[0]);
                fma2(acc[i][1], hh, bq[1]);
                fma2(acc[i][2], hh, bq[2]);
                fma2(acc[i][3], hh, bq[3]);
            }
        }
        __syncthreads();
        if (kc < 63) {
            #pragma unroll
            for (int p = 0; p < 2; p++) {
                int flat = tid * 4 + p * 1024;
                int o = flat >> 4, kk = flat & 15;
                Ws[(kk + 0) * WSROW + o] = rw[p].x;
                Ws[(kk + 1) * WSROW + o] = rw[p].y;
                Ws[(kk + 2) * WSROW + o] = rw[p].z;
                Ws[(kk + 3) * WSROW + o] = rw[p].w;
                int mk = flat >> 7, col = flat & 127;
                *(float4*)(ms + mk * 128 + col) = rm[p];
            }
            __syncthreads();
        }
    }

    // store: out flat = b*2097152 + o*16384 + (pix within batch)
    const int bz = n0 >> 14;
    const size_t base = (size_t)bz * (COUT * 16384) + (n0 & 16383);
    #pragma unroll
    for (int i = 0; i < 8; i++) {
        int o = ty * 8 + i;
        float* ob = out + base + (size_t)o * 16384;
        #pragma unroll
        for (int j = 0; j < 4; j++)
            *(unsigned long long*)(ob + tx * 2 + j * 32) = acc[i][j];
    }
}

extern "C" void kernel_launch(void* const* d_in, const int* in_sizes, int n_in,
                              void* d_out, int out_size) {
    const float* x  = (const float*)d_in[0];
    const float* r  = (const float*)d_in[1];
    const float* W1 = (const float*)d_in[2];
    const float* b1 = (const float*)d_in[3];
    const float* W2 = (const float*)d_in[4];
    const float* b2 = (const float*)d_in[5];
    const float* Wc = (const float*)d_in[6];
    const float* bc = (const float*)d_in[7];
    float* out = (float*)d_out;

    const int smem1 = SM1_FLOATS * 4;
    cudaFuncSetAttribute(k1_weights, cudaFuncAttributeMaxDynamicSharedMemorySize, smem1);

    float* rcout = (out_size > OUT0) ? (out + OUT0) : nullptr;

    dim3 g1(16, 32, 4);
    k1_weights<<<g1, 256, smem1>>>(x, r, W1, b1, W2, b2, rcout);
    k2_gemm<<<512, 256>>>(Wc, bc, out);
}

// round 2
// speedup vs baseline: 1.0649x; 1.0649x over previous
#include <cuda_runtime.h>
#include <cstdint>
#include <cstddef>

#define BATCH   4
#define CIN     64
#define COUT    128
#define HH      64
#define WW      1024
#define HO      32
#define WO      512
#define NPIX    65536
#define KTOT    1024
#define OUT0    8388608
#define AZI_C   0.006135923151542565f
#define INC_C   0.0073f

// scratch: mT[k][n], k = c*16 + pos, n = pixel index (b*16384 + ho*512 + wo)
__device__ float g_m[(size_t)KTOT * NPIX];

// ---- packed f32x2 helpers ----
__device__ __forceinline__ unsigned long long pk2(float a, float b) {
    unsigned long long d;
    asm("mov.b64 %0, {%1, %2};" : "=l"(d) : "r"(__float_as_uint(a)), "r"(__float_as_uint(b)));
    return d;
}
__device__ __forceinline__ void fma2(unsigned long long& d, unsigned long long a, unsigned long long b) {
    asm("fma.rn.f32x2 %0, %1, %2, %0;" : "+l"(d) : "l"(a), "l"(b));
}

// =====================================================================
// Kernel 1: h -> w (GEMM) -> m = w*x -> g_m, plus r_center.
// grid (16, 32, 4), 256 threads, 1 CTA/SM.
// Two sub-phases of 256 combos each (combo = posl*32 + px, pos = 8s+posl).
// smem (floats):
//   hs   [64][256]  h values (packed operand: combo pairs)
//   ws   [64c][256] w output
//   W2d  [64][128]  W2 duplicated along c (broadcast operand)
//   Ast  [64][16]   folded layer-1 weights, transposed
//   W10s[64] b1s[64] b2s[64] rs[4][66]
// =====================================================================
#define SM1_FLOATS (16384 + 16384 + 8192 + 1024 + 64 + 64 + 64 + 264)

__global__ void __launch_bounds__(256, 1)
k1_weights(const float* __restrict__ x, const float* __restrict__ r,
           const float* __restrict__ W1, const float* __restrict__ b1,
           const float* __restrict__ W2, const float* __restrict__ b2,
           float* __restrict__ rcout)
{
    extern __shared__ float sm[];
    float* hs   = sm;
    float* ws   = hs   + 16384;
    float* W2d  = ws   + 16384;
    float* Ast  = W2d  + 8192;
    float* W10s = Ast  + 1024;
    float* b1s  = W10s + 64;
    float* b2s  = b1s  + 64;
    float* rs   = b2s  + 64;     // [4][66]

    const int tid = threadIdx.x;
    const int ho  = blockIdx.y;
    const int bz  = blockIdx.z;
    const int wo0 = blockIdx.x * 32;

    // ---- stage constants ----
    for (int i = tid; i < 4096; i += 256) {
        int j = i >> 6, c = i & 63;
        float v = W2[i];
        W2d[j * 128 + 2 * c]     = v;
        W2d[j * 128 + 2 * c + 1] = v;
    }
    if (tid < 64) { W10s[tid] = W1[tid]; b1s[tid] = b1[tid]; b2s[tid] = b2[tid]; }
    for (int i = tid; i < 1024; i += 256) {
        int j = i >> 4, pos = i & 15;
        int u = pos >> 2, v = pos & 3;
        float du = (float)(u - 2), dv = (float)(v - 2);
        float ca = cosf(AZI_C * dv), sa = sinf(AZI_C * dv);
        float ci = cosf(INC_C * du), si = sinf(INC_C * du);
        Ast[i] = ca * ci * W1[j] + ca * si * W1[64 + j] + sa * W1[128 + j];
    }
    for (int i = tid; i < 4 * 66; i += 256) {
        int v = i / 66, cc = i % 66;
        int rowp = 2 * ho + v;
        int row  = (rowp == 0) ? (HH - 1) : ((rowp == HH + 1) ? 0 : rowp - 1);
        int colp = 2 * wo0 + cc;
        float val;
        if (colp == 0 || colp == WW + 1) val = 100.0f;
        else val = r[((size_t)bz * HH + row) * WW + (colp - 1)];
        rs[i] = val;
    }
    __syncthreads();

    int xr[4];
    #pragma unroll
    for (int v = 0; v < 4; v++) {
        int rowp = 2 * ho + v;
        xr[v] = (rowp == 0) ? (HH - 1) : ((rowp == HH + 1) ? 0 : rowp - 1);
    }
    const size_t nbase = (size_t)bz * 16384 + (size_t)ho * 512 + wo0;

    const int tx = tid & 31;   // combo-pair group (n dim)
    const int ty = tid >> 5;   // c group / warp id

    for (int s = 0; s < 2; s++) {
        // ---- hs compute: thread = one local combo, all 64 j ----
        {
            int posl = tid >> 5;             // 0..7
            int pos  = 8 * s + posl;
            int u = pos >> 2, v = pos & 3;
            int px = tid & 31;
            float R   = rs[v * 66 + 2 * px + u];
            float nrc = -rs[2 * 66 + 2 * px + 2];
            #pragma unroll 8
            for (int j = 0; j < 64; j++) {
                float t = fmaf(R, Ast[j * 16 + pos], fmaf(nrc, W10s[j], b1s[j]));
                hs[j * 256 + tid] = (t > 0.0f) ? t : 0.2f * t;
            }
        }
        __syncthreads();

        // ---- GEMM: W[c][combo] = b2 + sum_j W2[j][c] * h[j][combo] ----
        {
            unsigned long long acc[8][4];
            #pragma unroll
            for (int i = 0; i < 8; i++) {
                float bv = b2s[ty * 8 + i];
                unsigned long long bp = pk2(bv, bv);
                #pragma unroll
                for (int p = 0; p < 4; p++) acc[i][p] = bp;
            }
            #pragma unroll 4
            for (int j = 0; j < 64; j++) {
                const ulonglong2* wr = (const ulonglong2*)(W2d + j * 128 + ty * 16);
                ulonglong2 q0 = wr[0], q1 = wr[1], q2 = wr[2], q3 = wr[3];
                const ulonglong2* hr = (const ulonglong2*)(hs + j * 256 + tx * 8);
                ulonglong2 ha = hr[0], hb = hr[1];
                unsigned long long hv0 = ha.x, hv1 = ha.y, hv2 = hb.x, hv3 = hb.y;
                unsigned long long wv[8] = {q0.x, q0.y, q1.x, q1.y, q2.x, q2.y, q3.x, q3.y};
                #pragma unroll
                for (int i = 0; i < 8; i++) {
                    fma2(acc[i][0], wv[i], hv0);
                    fma2(acc[i][1], wv[i], hv1);
                    fma2(acc[i][2], wv[i], hv2);
                    fma2(acc[i][3], wv[i], hv3);
                }
            }
            #pragma unroll
            for (int i = 0; i < 8; i++) {
                ulonglong2* wp = (ulonglong2*)(ws + (ty * 8 + i) * 256 + tx * 8);
                ulonglong2 o0; o0.x = acc[i][0]; o0.y = acc[i][1];
                ulonglong2 o1; o1.x = acc[i][2]; o1.y = acc[i][3];
                wp[0] = o0; wp[1] = o1;
            }
        }
        __syncthreads();

        // ---- phase B: warp = posl, lane = px, loop c ----
        {
            int posl = ty;                    // 0..7
            int pos  = 8 * s + posl;
            int u = pos >> 2, v = pos & 3;
            int px = tx;
            int xcol = 2 * (wo0 + px) + u - 1;      // global col, -1..1024
            bool valid = (xcol >= 0) && (xcol < WW);
            const float* xbase = x + ((size_t)(bz * CIN) * HH + xr[v]) * WW + (valid ? xcol : 0);
            const float* wsr = ws + posl * 32 + px;
            float* gm = g_m + (size_t)pos * NPIX + nbase + px;
            #pragma unroll 4
            for (int c = 0; c < 64; c++) {
                float wv = wsr[c * 256];
                float xv = valid ? xbase[(size_t)c * (HH * WW)] : 0.0f;
                gm[(size_t)c * 16 * NPIX] = wv * xv;
            }
        }
        __syncthreads();
    }

    if (rcout != nullptr && tid < 32) {
        rcout[nbase + tid] = rs[2 * 66 + 2 * tid + 2];
    }
}

// =====================================================================
// Kernel 2: out[o][n] = bc[o] + sum_k Wc[o][k] * mT[k][n]
// Tile O=128 x N=128, Kc=16, duplicated-Ws so broadcast operand is LDS.128.
// grid 512 blocks, 256 threads.
// =====================================================================
#define WSD 264
__global__ void __launch_bounds__(256, 2)
k2_gemm(const float* __restrict__ Wc, const float* __restrict__ bc,
        float* __restrict__ out)
{
    __shared__ float Wsd[16 * WSD];    // [kk][o dup], padded
    __shared__ float ms[16 * 128];     // [kk][n]

    const int tid = threadIdx.x;
    const int tx = tid & 15;           // n group
    const int ty = tid >> 4;           // o group
    const int n0 = blockIdx.x * 128;

    unsigned long long acc[8][4];
    #pragma unroll
    for (int i = 0; i < 8; i++) {
        float bv = bc[ty * 8 + i];
        unsigned long long bp = pk2(bv, bv);
        #pragma unroll
        for (int j = 0; j < 4; j++) acc[i][j] = bp;
    }

    float4 rw[2], rm[2];

    #pragma unroll
    for (int p = 0; p < 2; p++) {
        int flat = tid * 4 + p * 1024;
        int o = flat >> 4, kk = flat & 15;
        rw[p] = *(const float4*)(Wc + (size_t)o * 1024 + kk);
        int mk = flat >> 7, col = flat & 127;
        rm[p] = *(const float4*)(g_m + (size_t)mk * NPIX + n0 + col);
    }
    #pragma unroll
    for (int p = 0; p < 2; p++) {
        int flat = tid * 4 + p * 1024;
        int o = flat >> 4, kk = flat & 15;
        float vv[4] = {rw[p].x, rw[p].y, rw[p].z, rw[p].w};
        #pragma unroll
        for (int i = 0; i < 4; i++)
            *(unsigned long long*)(Wsd + (kk + i) * WSD + o * 2) = pk2(vv[i], vv[i]);
        int mk = flat >> 7, col = flat & 127;
        *(float4*)(ms + mk * 128 + col) = rm[p];
    }
    __syncthreads();

    for (int kc = 0; kc < 64; kc++) {
        if (kc < 63) {
            int k0 = (kc + 1) * 16;
            #pragma unroll
            for (int p = 0; p < 2; p++) {
                int flat = tid * 4 + p * 1024;
                int o = flat >> 4, kk = flat & 15;
                rw[p] = *(const float4*)(Wc + (size_t)o * 1024 + k0 + kk);
                int mk = flat >> 7, col = flat & 127;
                rm[p] = *(const float4*)(g_m + (size_t)(k0 + mk) * NPIX + n0 + col);
            }
        }
        #pragma unroll
        for (int kk = 0; kk < 16; kk++) {
            const ulonglong2* wr = (const ulonglong2*)(Wsd + kk * WSD + ty * 16);
            ulonglong2 q0 = wr[0], q1 = wr[1], q2 = wr[2], q3 = wr[3];
            unsigned long long wv[8] = {q0.x, q0.y, q1.x, q1.y, q2.x, q2.y, q3.x, q3.y};
            unsigned long long bq[4];
            #pragma unroll
            for (int j = 0; j < 4; j++)
                bq[j] = *(const unsigned long long*)(ms + kk * 128 + tx * 2 + j * 32);
            #pragma unroll
            for (int i = 0; i < 8; i++) {
                fma2(acc[i][0], wv[i], bq[0]);
                fma2(acc[i][1], wv[i], bq[1]);
                fma2(acc[i][2], wv[i], bq[2]);
                fma2(acc[i][3], wv[i], bq[3]);
            }
        }
        __syncthreads();
        if (kc < 63) {
            #pragma unroll
            for (int p = 0; p < 2; p++) {
                int flat = tid * 4 + p * 1024;
                int o = flat >> 4, kk = flat & 15;
                float vv[4] = {rw[p].x, rw[p].y, rw[p].z, rw[p].w};
                #pragma unroll
                for (int i = 0; i < 4; i++)
                    *(unsigned long long*)(Wsd + (kk + i) * WSD + o * 2) = pk2(vv[i], vv[i]);
                int mk = flat >> 7, col = flat & 127;
                *(float4*)(ms + mk * 128 + col) = rm[p];
            }
            __syncthreads();
        }
    }

    const int bz = n0 >> 14;
    const size_t base = (size_t)bz * (COUT * 16384) + (n0 & 16383);
    #pragma unroll
    for (int i = 0; i < 8; i++) {
        int o = ty * 8 + i;
        float* ob = out + base + (size_t)o * 16384;
        #pragma unroll
        for (int j = 0; j < 4; j++)
            *(unsigned long long*)(ob + tx * 2 + j * 32) = acc[i][j];
    }
}

extern "C" void kernel_launch(void* const* d_in, const int* in_sizes, int n_in,
                              void* d_out, int out_size) {
    const float* x  = (const float*)d_in[0];
    const float* r  = (const float*)d_in[1];
    const float* W1 = (const float*)d_in[2];
    const float* b1 = (const float*)d_in[3];
    const float* W2 = (const float*)d_in[4];
    const float* b2 = (const float*)d_in[5];
    const float* Wc = (const float*)d_in[6];
    const float* bc = (const float*)d_in[7];
    float* out = (float*)d_out;

    const int smem1 = SM1_FLOATS * 4;
    cudaFuncSetAttribute(k1_weights, cudaFuncAttributeMaxDynamicSharedMemorySize, smem1);

    float* rcout = (out_size > OUT0) ? (out + OUT0) : nullptr;

    dim3 g1(16, 32, 4);
    k1_weights<<<g1, 256, smem1>>>(x, r, W1, b1, W2, b2, rcout);
    k2_gemm<<<512, 256>>>(Wc, bc, out);
}

// round 4
// speedup vs baseline: 1.4700x; 1.3804x over previous
#include <cuda_runtime.h>
#include <cuda_bf16.h>
#include <cstdint>
#include <cstddef>

#define BATCH   4
#define CIN     64
#define COUT    128
#define HH      64
#define WW      1024
#define HO      32
#define WO      512
#define NPIX    65536
#define KTOT    1024
#define OUT0    8388608
#define AZI_C   0.006135923151542565f
#define INC_C   0.0073f

// scratch: m split into bf16 hi/lo planes, [k][n] layout, n contiguous
__device__ __nv_bfloat16 g_mh[(size_t)KTOT * NPIX];
__device__ __nv_bfloat16 g_ml[(size_t)KTOT * NPIX];
__device__ __nv_bfloat16 g_WcH[COUT * KTOT];
__device__ __nv_bfloat16 g_WcL[COUT * KTOT];

// ---- packed f32x2 helpers (k1) ----
__device__ __forceinline__ unsigned long long pk2(float a, float b) {
    unsigned long long d;
    asm("mov.b64 %0, {%1, %2};" : "=l"(d) : "r"(__float_as_uint(a)), "r"(__float_as_uint(b)));
    return d;
}
__device__ __forceinline__ void fma2(unsigned long long& d, unsigned long long a, unsigned long long b) {
    asm("fma.rn.f32x2 %0, %1, %2, %0;" : "+l"(d) : "l"(a), "l"(b));
}

__device__ __forceinline__ uint32_t smem_u32(const void* p) {
    uint32_t a;
    asm("{ .reg .u64 t; cvta.to.shared.u64 t, %1; cvt.u32.u64 %0, t; }" : "=r"(a) : "l"(p));
    return a;
}
// swizzles: A rows are 128B (bits[6:4] ^= bits[9:7]); B rows are 256B (bits[6:4] ^= bits[10:8])
#define SWA(o) ((o) ^ (((o) >> 3) & 0x70))
#define SWB(o) ((o) ^ (((o) >> 4) & 0x70))

__device__ __forceinline__ void cp16(uint32_t saddr, const void* gaddr) {
    asm volatile("cp.async.cg.shared.global [%0], [%1], 16;" :: "r"(saddr), "l"(gaddr));
}
#define CP_COMMIT() asm volatile("cp.async.commit_group;" ::: "memory")
#define CP_WAIT1()  asm volatile("cp.async.wait_group 1;" ::: "memory")
#define CP_WAIT0()  asm volatile("cp.async.wait_group 0;" ::: "memory")

__device__ __forceinline__ void ldsm4(uint32_t* r, uint32_t a) {
    asm volatile("ldmatrix.sync.aligned.m8n8.x4.shared.b16 {%0,%1,%2,%3}, [%4];"
        : "=r"(r[0]), "=r"(r[1]), "=r"(r[2]), "=r"(r[3]) : "r"(a));
}
__device__ __forceinline__ void ldsm4t(uint32_t* r, uint32_t a) {
    asm volatile("ldmatrix.sync.aligned.m8n8.x4.trans.shared.b16 {%0,%1,%2,%3}, [%4];"
        : "=r"(r[0]), "=r"(r[1]), "=r"(r[2]), "=r"(r[3]) : "r"(a));
}
__device__ __forceinline__ void mma16816(float* d, const uint32_t* a, const uint32_t* b) {
    asm volatile(
        "mma.sync.aligned.m16n8k16.row.col.f32.bf16.bf16.f32 "
        "{%0,%1,%2,%3}, {%4,%5,%6,%7}, {%8,%9}, {%0,%1,%2,%3};"
        : "+f"(d[0]), "+f"(d[1]), "+f"(d[2]), "+f"(d[3])
        : "r"(a[0]), "r"(a[1]), "r"(a[2]), "r"(a[3]), "r"(b[0]), "r"(b[1]));
}

// =====================================================================
// Kernel 0: split Wc into bf16 hi/lo ([o][k], k contiguous)
// =====================================================================
__global__ void k0_prep(const float* __restrict__ Wc) {
    int i = blockIdx.x * 256 + threadIdx.x;
    if (i < COUT * KTOT) {
        float v = Wc[i];
        __nv_bfloat16 h = __float2bfloat16(v);
        g_WcH[i] = h;
        g_WcL[i] = __float2bfloat16(v - __bfloat162float(h));
    }
}

// =====================================================================
// Kernel 1: h -> w (GEMM) -> m = w*x -> g_mh/g_ml, plus r_center.
// grid (16, 32, 4), 256 threads, 1 CTA/SM.
// =====================================================================
#define SM1_FLOATS (16384 + 16384 + 8192 + 1024 + 64 + 64 + 64 + 264)

__global__ void __launch_bounds__(256, 1)
k1_weights(const float* __restrict__ x, const float* __restrict__ r,
           const float* __restrict__ W1, const float* __restrict__ b1,
           const float* __restrict__ W2, const float* __restrict__ b2,
           float* __restrict__ rcout)
{
    extern __shared__ float sm[];
    float* hs   = sm;
    float* ws   = hs   + 16384;
    float* W2d  = ws   + 16384;
    float* Ast  = W2d  + 8192;
    float* W10s = Ast  + 1024;
    float* b1s  = W10s + 64;
    float* b2s  = b1s  + 64;
    float* rs   = b2s  + 64;

    const int tid = threadIdx.x;
    const int ho  = blockIdx.y;
    const int bz  = blockIdx.z;
    const int wo0 = blockIdx.x * 32;

    for (int i = tid; i < 4096; i += 256) {
        int j = i >> 6, c = i & 63;
        float v = W2[i];
        W2d[j * 128 + 2 * c]     = v;
        W2d[j * 128 + 2 * c + 1] = v;
    }
    if (tid < 64) { W10s[tid] = W1[tid]; b1s[tid] = b1[tid]; b2s[tid] = b2[tid]; }
    for (int i = tid; i < 1024; i += 256) {
        int j = i >> 4, pos = i & 15;
        int u = pos >> 2, v = pos & 3;
        float du = (float)(u - 2), dv = (float)(v - 2);
        float ca = cosf(AZI_C * dv), sa = sinf(AZI_C * dv);
        float ci = cosf(INC_C * du), si = sinf(INC_C * du);
        Ast[i] = ca * ci * W1[j] + ca * si * W1[64 + j] + sa * W1[128 + j];
    }
    for (int i = tid; i < 4 * 66; i += 256) {
        int v = i / 66, cc = i % 66;
        int rowp = 2 * ho + v;
        int row  = (rowp == 0) ? (HH - 1) : ((rowp == HH + 1) ? 0 : rowp - 1);
        int colp = 2 * wo0 + cc;
        float val;
        if (colp == 0 || colp == WW + 1) val = 100.0f;
        else val = r[((size_t)bz * HH + row) * WW + (colp - 1)];
        rs[i] = val;
    }
    __syncthreads();

    int xr[4];
    #pragma unroll
    for (int v = 0; v < 4; v++) {
        int rowp = 2 * ho + v;
        xr[v] = (rowp == 0) ? (HH - 1) : ((rowp == HH + 1) ? 0 : rowp - 1);
    }
    const size_t nbase = (size_t)bz * 16384 + (size_t)ho * 512 + wo0;

    const int tx = tid & 31;
    const int ty = tid >> 5;

    for (int s = 0; s < 2; s++) {
        {   // hs
            int posl = tid >> 5;
            int pos  = 8 * s + posl;
            int u = pos >> 2, v = pos & 3;
            int px = tid & 31;
            float R   = rs[v * 66 + 2 * px + u];
            float nrc = -rs[2 * 66 + 2 * px + 2];
            #pragma unroll 8
            for (int j = 0; j < 64; j++) {
                float t = fmaf(R, Ast[j * 16 + pos], fmaf(nrc, W10s[j], b1s[j]));
                hs[j * 256 + tid] = (t > 0.0f) ? t : 0.2f * t;
            }
        }
        __syncthreads();

        {   // GEMM -> ws
            unsigned long long acc[8][4];
            #pragma unroll
            for (int i = 0; i < 8; i++) {
                float bv = b2s[ty * 8 + i];
                unsigned long long bp = pk2(bv, bv);
                #pragma unroll
                for (int p = 0; p < 4; p++) acc[i][p] = bp;
            }
            #pragma unroll 4
            for (int j = 0; j < 64; j++) {
                const ulonglong2* wr = (const ulonglong2*)(W2d + j * 128 + ty * 16);
                ulonglong2 q0 = wr[0], q1 = wr[1], q2 = wr[2], q3 = wr[3];
                const ulonglong2* hr = (const ulonglong2*)(hs + j * 256 + tx * 8);
                ulonglong2 ha = hr[0], hb = hr[1];
                unsigned long long hv0 = ha.x, hv1 = ha.y, hv2 = hb.x, hv3 = hb.y;
                unsigned long long wv[8] = {q0.x, q0.y, q1.x, q1.y, q2.x, q2.y, q3.x, q3.y};
                #pragma unroll
                for (int i = 0; i < 8; i++) {
                    fma2(acc[i][0], wv[i], hv0);
                    fma2(acc[i][1], wv[i], hv1);
                    fma2(acc[i][2], wv[i], hv2);
                    fma2(acc[i][3], wv[i], hv3);
                }
            }
            #pragma unroll
            for (int i = 0; i < 8; i++) {
                ulonglong2* wp = (ulonglong2*)(ws + (ty * 8 + i) * 256 + tx * 8);
                ulonglong2 o0; o0.x = acc[i][0]; o0.y = acc[i][1];
                ulonglong2 o1; o1.x = acc[i][2]; o1.y = acc[i][3];
                wp[0] = o0; wp[1] = o1;
            }
        }
        __syncthreads();

        {   // phase B: m = w*x -> bf16 hi/lo
            int posl = ty;
            int pos  = 8 * s + posl;
            int u = pos >> 2, v = pos & 3;
            int px = tx;
            int xcol = 2 * (wo0 + px) + u - 1;
            bool valid = (xcol >= 0) && (xcol < WW);
            const float* xbase = x + ((size_t)(bz * CIN) * HH + xr[v]) * WW + (valid ? xcol : 0);
            const float* wsr = ws + posl * 32 + px;
            __nv_bfloat16* gmh = g_mh + (size_t)pos * NPIX + nbase + px;
            __nv_bfloat16* gml = g_ml + (size_t)pos * NPIX + nbase + px;
            #pragma unroll 4
            for (int c = 0; c < 64; c++) {
                float wv = wsr[c * 256];
                float xv = valid ? xbase[(size_t)c * (HH * WW)] : 0.0f;
                float mv = wv * xv;
                __nv_bfloat16 hi = __float2bfloat16(mv);
                float rem = mv - __bfloat162float(hi);
                gmh[(size_t)c * 16 * NPIX] = hi;
                gml[(size_t)c * 16 * NPIX] = __float2bfloat16(rem);
            }
        }
        __syncthreads();
    }

    if (rcout != nullptr && tid < 32) {
        rcout[nbase + tid] = rs[2 * 66 + 2 * tid + 2];
    }
}

// =====================================================================
// Kernel 2: HMMA bf16 split GEMM (mma.sync.m16n8k16).
// out[o][n] = bc[o] + sum_k Wc[o][k]*m[k][n],  hi*hi + hi*lo + lo*hi.
// grid 512 CTAs (N-tile 128), 256 threads (8 warps = 4M x 2N).
// smem/stage 64KB: Ah[128][64] | Al | Bh[64][128] | Bl ; double-buffered.
// =====================================================================
#define K2_STAGE 65536
#define K2_SMEM  (2 * K2_STAGE)

__global__ void __launch_bounds__(256, 1)
k2_hmma(const float* __restrict__ bc, float* __restrict__ out)
{
    extern __shared__ char sm2[];
    const uint32_t sb = smem_u32(sm2);
    const int tid  = threadIdx.x;
    const int wid  = tid >> 5;
    const int lane = tid & 31;
    const int n0 = blockIdx.x * 128;
    const int wm = (wid & 3) * 32;     // warp M offset (o)
    const int wn = (wid >> 2) * 64;    // warp N offset

    float acc[2][8][4];
    #pragma unroll
    for (int mi = 0; mi < 2; mi++)
        #pragma unroll
        for (int nt = 0; nt < 8; nt++)
            #pragma unroll
            for (int q = 0; q < 4; q++) acc[mi][nt][q] = 0.0f;

    auto load_chunk = [&](int c, int s) {
        const uint32_t base = sb + s * K2_STAGE;
        const int k0 = c * 64;
        #pragma unroll
        for (int t = 0; t < 16; t++) {
            int ci  = tid + t * 256;
            int sec = t >> 2;            // 0:Ah 1:Al 2:Bh 3:Bl
            int ci0 = ci & 1023;
            if (sec < 2) {
                const __nv_bfloat16* W = sec ? g_WcL : g_WcH;
                int row = ci0 >> 3, u = ci0 & 7;
                uint32_t sa = base + sec * 16384 + SWA(row * 128 + u * 16);
                cp16(sa, W + (size_t)row * KTOT + k0 + u * 8);
            } else {
                const __nv_bfloat16* M = (sec == 2) ? g_mh : g_ml;
                int row = ci0 >> 4, u = ci0 & 15;
                uint32_t sa = base + sec * 16384 + SWB(row * 256 + u * 16);
                cp16(sa, M + (size_t)(k0 + row) * NPIX + n0 + u * 8);
            }
        }
        CP_COMMIT();
    };

    load_chunk(0, 0);
    load_chunk(1, 1);

    for (int c = 0; c < 16; c++) {
        const int s = c & 1;
        if (c == 15) { CP_WAIT0(); } else { CP_WAIT1(); }
        __syncthreads();

        const uint32_t bAh = sb + s * K2_STAGE;
        const uint32_t bAl = bAh + 16384;
        const uint32_t bBh = bAh + 32768;
        const uint32_t bBl = bAh + 49152;

        #pragma unroll
        for (int ks = 0; ks < 4; ks++) {
            uint32_t a_h[2][4], a_l[2][4];
            {
                int arow  = wm + (lane & 15);
                int acolb = ks * 32 + ((lane >> 4) << 4);
                #pragma unroll
                for (int mi = 0; mi < 2; mi++) {
                    uint32_t off = SWA((arow + mi * 16) * 128 + acolb);
                    ldsm4(a_h[mi], bAh + off);
                    ldsm4(a_l[mi], bAl + off);
                }
            }
            int brow = ks * 16 + (lane & 15);
            #pragma unroll
            for (int g = 0; g < 4; g++) {
                int bcolb = (wn + g * 16 + ((lane >> 4) << 3)) * 2;
                uint32_t off = SWB(brow * 256 + bcolb);
                uint32_t bh[4], bl[4];
                ldsm4t(bh, bBh + off);
                ldsm4t(bl, bBl + off);
                #pragma unroll
                for (int mi = 0; mi < 2; mi++) {
                    mma16816(acc[mi][2*g],   a_h[mi], bh);
                    mma16816(acc[mi][2*g+1], a_h[mi], bh + 2);
                    mma16816(acc[mi][2*g],   a_l[mi], bh);
                    mma16816(acc[mi][2*g+1], a_l[mi], bh + 2);
                    mma16816(acc[mi][2*g],   a_h[mi], bl);
                    mma16816(acc[mi][2*g+1], a_h[mi], bl + 2);
                }
            }
        }
        __syncthreads();
        if (c + 2 < 16) load_chunk(c + 2, s);
    }

    // epilogue: bias + store
    const int bz = n0 >> 14;
    #pragma unroll
    for (int mi = 0; mi < 2; mi++) {
        int r0 = wm + mi * 16 + (lane >> 2);
        float bv0 = bc[r0], bv1 = bc[r0 + 8];
        float* row0 = out + ((size_t)(bz * COUT + r0))     * 16384 + (n0 & 16383);
        float* row1 = out + ((size_t)(bz * COUT + r0 + 8)) * 16384 + (n0 & 16383);
        #pragma unroll
        for (int nt = 0; nt < 8; nt++) {
            int col = wn + nt * 8 + (lane & 3) * 2;
            float2 v0, v1;
            v0.x = acc[mi][nt][0] + bv0; v0.y = acc[mi][nt][1] + bv0;
            v1.x = acc[mi][nt][2] + bv1; v1.y = acc[mi][nt][3] + bv1;
            *(float2*)(row0 + col) = v0;
            *(float2*)(row1 + col) = v1;
        }
    }
}

extern "C" void kernel_launch(void* const* d_in, const int* in_sizes, int n_in,
                              void* d_out, int out_size) {
    const float* x  = (const float*)d_in[0];
    const float* r  = (const float*)d_in[1];
    const float* W1 = (const float*)d_in[2];
    const float* b1 = (const float*)d_in[3];
    const float* W2 = (const float*)d_in[4];
    const float* b2 = (const float*)d_in[5];
    const float* Wc = (const float*)d_in[6];
    const float* bc = (const float*)d_in[7];
    float* out = (float*)d_out;

    const int smem1 = SM1_FLOATS * 4;
    cudaFuncSetAttribute(k1_weights, cudaFuncAttributeMaxDynamicSharedMemorySize, smem1);
    cudaFuncSetAttribute(k2_hmma, cudaFuncAttributeMaxDynamicSharedMemorySize, K2_SMEM);

    float* rcout = (out_size > OUT0) ? (out + OUT0) : nullptr;

    k0_prep<<<(COUT * KTOT + 255) / 256, 256>>>(Wc);
    dim3 g1(16, 32, 4);
    k1_weights<<<g1, 256, smem1>>>(x, r, W1, b1, W2, b2, rcout);
    k2_hmma<<<512, 256, K2_SMEM>>>(bc, out);
}